// round 13
// baseline (speedup 1.0000x reference)
#include <cuda_runtime.h>

#define CH 64
#define NMAX 100000
#define EMAX 1200000
#define SCAN_B 1024

// Scratch (allocation-free rule: __device__ globals)
__device__ float g_h1[NMAX * CH];
__device__ float g_mean[NMAX * CH];
__device__ float g_xf[NMAX * CH];     // nan_to_num(x), written by init
__device__ int   g_deg[NMAX];
__device__ int   g_cur[NMAX];
__device__ int   g_rowptr[NMAX + 1];
__device__ int   g_csr[EMAX];
__device__ int   g_bsum[128];
__device__ int   g_is64;

// ---------------------------------------------------------------------------
// f32x2 packed helpers (sm_103a: FFMA2 reachable only via PTX fma.rn.f32x2)
// ---------------------------------------------------------------------------
__device__ __forceinline__ unsigned long long pk2(float lo, float hi) {
    unsigned long long r;
    asm("mov.b64 %0, {%1, %2};" : "=l"(r) : "f"(lo), "f"(hi));
    return r;
}
__device__ __forceinline__ void fma2(unsigned long long& d,
                                     unsigned long long a,
                                     unsigned long long b) {
    asm("fma.rn.f32x2 %0, %1, %2, %0;" : "+l"(d) : "l"(a), "l"(b));
}
__device__ __forceinline__ float2 up2(unsigned long long v) {
    float2 r;
    asm("mov.b64 {%0, %1}, %2;" : "=f"(r.x), "=f"(r.y) : "l"(v));
    return r;
}

// ---------------------------------------------------------------------------
// init: g_xf = nan_to_num(x); zero g_deg; detect int64 vs int32 edge_index.
// ---------------------------------------------------------------------------
__global__ void init_kernel(const void* idx, const float* __restrict__ x,
                            int nNodes) {
    int tid = blockIdx.x * blockDim.x + threadIdx.x;
    int total4 = nNodes * CH / 4;
    for (int t = tid; t < total4; t += gridDim.x * blockDim.x) {
        float4 v = ((const float4*)x)[t];
        if (v.x != v.x) v.x = 0.0f;
        if (v.y != v.y) v.y = 0.0f;
        if (v.z != v.z) v.z = 0.0f;
        if (v.w != v.w) v.w = 0.0f;
        ((float4*)g_xf)[t] = v;
    }
    if (tid < nNodes) g_deg[tid] = 0;
    if (tid == 0) {
        const long long* p = (const long long*)idx;
        int is64 = 1;
        for (int t = 0; t < 1024; t++) {
            long long v = p[t];
            if (v < 0 || v >= (long long)nNodes) { is64 = 0; break; }
        }
        g_is64 = is64;
    }
}

__device__ __forceinline__ void load_edge(const void* idx, int nEdges, int e,
                                          int& s, int& d) {
    if (g_is64) {
        const long long* p = (const long long*)idx;
        s = (int)p[e];
        d = (int)p[nEdges + e];
    } else {
        const int* p = (const int*)idx;
        s = p[e];
        d = p[nEdges + e];
    }
}

__global__ void count_kernel(const void* __restrict__ idx, int nEdges) {
    int e = blockIdx.x * blockDim.x + threadIdx.x;
    if (e >= nEdges) return;
    int s, d;
    load_edge(idx, nEdges, e, s, d);
    atomicAdd(&g_deg[d], 1);
}

// ---- 2-phase exclusive scan of g_deg into g_rowptr -------------------------
__global__ void scan_block_kernel(int n) {
    __shared__ int sh[SCAN_B];
    int i = blockIdx.x * SCAN_B + threadIdx.x;
    int v = (i < n) ? g_deg[i] : 0;
    sh[threadIdx.x] = v;
    __syncthreads();
    for (int off = 1; off < SCAN_B; off <<= 1) {
        int t = (threadIdx.x >= off) ? sh[threadIdx.x - off] : 0;
        __syncthreads();
        sh[threadIdx.x] += t;
        __syncthreads();
    }
    if (i < n) g_rowptr[i] = sh[threadIdx.x] - v;
    if (threadIdx.x == SCAN_B - 1) g_bsum[blockIdx.x] = sh[SCAN_B - 1];
}

__global__ void scan_finish_kernel(int n, int nEdges) {
    __shared__ int sOff;
    if (threadIdx.x < 32) {
        int acc = 0;
        for (int b = threadIdx.x; b < blockIdx.x; b += 32) acc += g_bsum[b];
#pragma unroll
        for (int o = 16; o > 0; o >>= 1)
            acc += __shfl_down_sync(0xffffffffu, acc, o);
        if (threadIdx.x == 0) sOff = acc;
    }
    __syncthreads();
    int i = blockIdx.x * SCAN_B + threadIdx.x;
    if (i < n) {
        int v = g_rowptr[i] + sOff;
        g_rowptr[i] = v;
        g_cur[i] = v;
    }
    if (i == 0) g_rowptr[n] = nEdges;
}

__global__ void fill_kernel(const void* __restrict__ idx, int nEdges) {
    int e = blockIdx.x * blockDim.x + threadIdx.x;
    if (e >= nEdges) return;
    int s, d;
    load_edge(idx, nEdges, e, s, d);
    int pos = atomicAdd(&g_cur[d], 1);
    g_csr[pos] = s;
}

// ---------------------------------------------------------------------------
// Aggregate: warp per node; lane owns channels (2*lane, 2*lane+1).
// UNCHANGED (validated); nanFix removed (x pre-fixed into g_xf).
// ---------------------------------------------------------------------------
__global__ void __launch_bounds__(256)
aggregate_kernel(const float* __restrict__ feat, int nNodes, int nanFix) {
    int node = blockIdx.x * 8 + (threadIdx.x >> 5);
    int lane = threadIdx.x & 31;
    if (node >= nNodes) return;

    int r0 = g_rowptr[node];
    int r1 = g_rowptr[node + 1];
    const float2* f2 = (const float2*)feat;

    float ax = 0.0f, ay = 0.0f;
    for (int base = r0; base < r1; base += 32) {
        int cnt = min(32, r1 - base);
        int sidx = (base + lane < r1) ? g_csr[base + lane] : 0;
        for (int i = 0; i < cnt; i += 8) {
            int s0 = __shfl_sync(0xffffffffu, sidx, i);
            int s1 = __shfl_sync(0xffffffffu, sidx, i + 1);
            int s2 = __shfl_sync(0xffffffffu, sidx, i + 2);
            int s3 = __shfl_sync(0xffffffffu, sidx, i + 3);
            int s4 = __shfl_sync(0xffffffffu, sidx, i + 4);
            int s5 = __shfl_sync(0xffffffffu, sidx, i + 5);
            int s6 = __shfl_sync(0xffffffffu, sidx, i + 6);
            int s7 = __shfl_sync(0xffffffffu, sidx, i + 7);
            float2 v0 = f2[(size_t)s0 * 32 + lane];
            float2 v1 = f2[(size_t)s1 * 32 + lane];
            float2 v2 = f2[(size_t)s2 * 32 + lane];
            float2 v3 = f2[(size_t)s3 * 32 + lane];
            float2 v4 = f2[(size_t)s4 * 32 + lane];
            float2 v5 = f2[(size_t)s5 * 32 + lane];
            float2 v6 = f2[(size_t)s6 * 32 + lane];
            float2 v7 = f2[(size_t)s7 * 32 + lane];
            float m1 = (i + 1 < cnt) ? 1.0f : 0.0f;
            float m2 = (i + 2 < cnt) ? 1.0f : 0.0f;
            float m3 = (i + 3 < cnt) ? 1.0f : 0.0f;
            float m4 = (i + 4 < cnt) ? 1.0f : 0.0f;
            float m5 = (i + 5 < cnt) ? 1.0f : 0.0f;
            float m6 = (i + 6 < cnt) ? 1.0f : 0.0f;
            float m7 = (i + 7 < cnt) ? 1.0f : 0.0f;
            ax += v0.x + m1 * v1.x + m2 * v2.x + m3 * v3.x
                + m4 * v4.x + m5 * v5.x + m6 * v6.x + m7 * v7.x;
            ay += v0.y + m1 * v1.y + m2 * v2.y + m3 * v3.y
                + m4 * v4.y + m5 * v5.y + m6 * v6.y + m7 * v7.y;
        }
    }

    int deg = r1 - r0;
    float inv = 1.0f / (float)((deg > 1) ? deg : 1);
    float2 out;
    out.x = ax * inv;
    out.y = ay * inv;
    ((float2*)g_mean)[(size_t)node * 32 + lane] = out;
}

// ---------------------------------------------------------------------------
// GEMM v2 — k-pair packed FFMA2, smem-light (fixes measured L1=81%).
// Lane owns channels {lane, lane+32}; warp owns 16 nodes; block = 4 warps.
// f32x2 lanes hold (even-k partial, odd-k partial) so A-pairs come straight
// from broadcast LDG.128 (no shfl/dup) and weights are k-pair packed in smem,
// loaded into registers once per 2-kp chunk and reused over 16 nodes.
// ---------------------------------------------------------------------------
__global__ void __launch_bounds__(128)
gemm_kernel(const float* __restrict__ mean,
            const float* __restrict__ xsrc,
            const float* __restrict__ Wl,
            const float* __restrict__ bias,
            const float* __restrict__ Wr,
            const float* __restrict__ Wfc,
            const float* __restrict__ bfc,
            float* __restrict__ pred,
            int nNodes, int layer) {
    // sWlp[kp*CH + j] = (Wl[2kp][j], Wl[2kp+1][j])
    __shared__ unsigned long long sWlp[(CH / 2) * CH];
    __shared__ unsigned long long sWrp[(CH / 2) * CH];
    for (int i = threadIdx.x; i < (CH / 2) * CH; i += 128) {
        int kp = i >> 6;
        int j = i & 63;
        sWlp[i] = pk2(Wl[(2 * kp) * CH + j], Wl[(2 * kp + 1) * CH + j]);
        sWrp[i] = pk2(Wr[(2 * kp) * CH + j], Wr[(2 * kp + 1) * CH + j]);
    }
    __syncthreads();

    int lane = threadIdx.x & 31;
    int warp = threadIdx.x >> 5;
    int tileBase = blockIdx.x * 64 + warp * 16;

    // acc[n][0] = channel `lane`, acc[n][1] = channel `lane+32`
    // each ull = (sum over even k, sum over odd k); bias seeded into even half
    unsigned long long acc[16][2];
    unsigned long long b0 = pk2(bias[lane], 0.0f);
    unsigned long long b1 = pk2(bias[lane + 32], 0.0f);
#pragma unroll
    for (int n = 0; n < 16; n++) { acc[n][0] = b0; acc[n][1] = b1; }

    for (int kp = 0; kp < CH / 2; kp += 2) {
        unsigned long long wla0 = sWlp[kp * CH + lane];
        unsigned long long wla1 = sWlp[(kp + 1) * CH + lane];
        unsigned long long wlb0 = sWlp[kp * CH + lane + 32];
        unsigned long long wlb1 = sWlp[(kp + 1) * CH + lane + 32];
        unsigned long long wra0 = sWrp[kp * CH + lane];
        unsigned long long wra1 = sWrp[(kp + 1) * CH + lane];
        unsigned long long wrb0 = sWrp[kp * CH + lane + 32];
        unsigned long long wrb1 = sWrp[(kp + 1) * CH + lane + 32];
#pragma unroll
        for (int n = 0; n < 16; n++) {
            int node = tileBase + n;
            int nc = (node < nNodes) ? node : 0;   // clamp; discarded at store
            ulonglong2 am =
                *(const ulonglong2*)(mean + (size_t)nc * CH + 2 * kp);
            ulonglong2 ax =
                *(const ulonglong2*)(xsrc + (size_t)nc * CH + 2 * kp);
            fma2(acc[n][0], am.x, wla0);
            fma2(acc[n][0], am.y, wla1);
            fma2(acc[n][0], ax.x, wra0);
            fma2(acc[n][0], ax.y, wra1);
            fma2(acc[n][1], am.x, wlb0);
            fma2(acc[n][1], am.y, wlb1);
            fma2(acc[n][1], ax.x, wrb0);
            fma2(acc[n][1], ax.y, wrb1);
        }
    }

    if (layer == 1) {
#pragma unroll
        for (int n = 0; n < 16; n++) {
            int node = tileBase + n;
            if (node < nNodes) {
                float2 ca = up2(acc[n][0]);
                float2 cb = up2(acc[n][1]);
                g_h1[(size_t)node * CH + lane]      = fmaxf(ca.x + ca.y, 0.0f);
                g_h1[(size_t)node * CH + lane + 32] = fmaxf(cb.x + cb.y, 0.0f);
            }
        }
    } else {
        float wfa = Wfc[lane];
        float wfb = Wfc[lane + 32];
        float bf = bfc[0];
#pragma unroll
        for (int n = 0; n < 16; n++) {
            float2 ca = up2(acc[n][0]);
            float2 cb = up2(acc[n][1]);
            float p = fmaxf(ca.x + ca.y, 0.0f) * wfa
                    + fmaxf(cb.x + cb.y, 0.0f) * wfb;
            p += __shfl_down_sync(0xffffffffu, p, 16);
            p += __shfl_down_sync(0xffffffffu, p, 8);
            p += __shfl_down_sync(0xffffffffu, p, 4);
            p += __shfl_down_sync(0xffffffffu, p, 2);
            p += __shfl_down_sync(0xffffffffu, p, 1);
            int node = tileBase + n;
            if (lane == 0 && node < nNodes) pred[node] = p + bf;
        }
    }
}

// ---------------------------------------------------------------------------
// Launch: CSR build = validated separate kernels (fused version measured
// +17us slower). 9 launches; ncu empirically captures launch #4.
// ---------------------------------------------------------------------------
extern "C" void kernel_launch(void* const* d_in, const int* in_sizes, int n_in,
                              void* d_out, int out_size) {
    const float* x   = (const float*)d_in[0];
    const void*  eix = d_in[1];
    const float* W1l = (const float*)d_in[2];
    const float* b1  = (const float*)d_in[3];
    const float* W1r = (const float*)d_in[4];
    const float* W2l = (const float*)d_in[5];
    const float* b2  = (const float*)d_in[6];
    const float* W2r = (const float*)d_in[7];
    const float* Wfc = (const float*)d_in[8];
    const float* bfc = (const float*)d_in[9];
    float* pred = (float*)d_out;

    int nNodes = in_sizes[0] / CH;   // 100000
    int nEdges = in_sizes[1] / 2;    // 1200000

    int edgeBlocks = (nEdges + 255) / 256;
    int scanBlocks = (nNodes + SCAN_B - 1) / SCAN_B;
    int aggBlocks  = (nNodes + 7) / 8;
    int gemmBlocks = (nNodes + 63) / 64;
    int initBlocks = (nNodes * CH / 4 + 255) / 256;   // one float4 per thread

    float* d_mean;
    cudaGetSymbolAddress((void**)&d_mean, g_mean);
    float* d_h1;
    cudaGetSymbolAddress((void**)&d_h1, g_h1);
    float* d_xf;
    cudaGetSymbolAddress((void**)&d_xf, g_xf);

    // x-fix + CSR build (dst -> list of src), reused by both layers
    init_kernel<<<initBlocks, 256>>>(eix, x, nNodes);          // 1
    count_kernel<<<edgeBlocks, 256>>>(eix, nEdges);            // 2
    scan_block_kernel<<<scanBlocks, SCAN_B>>>(nNodes);         // 3
    scan_finish_kernel<<<scanBlocks, SCAN_B>>>(nNodes, nEdges);// 4 <- profiled
    fill_kernel<<<edgeBlocks, 256>>>(eix, nEdges);             // 5

    // Layer 1 (all inputs NaN-clean via g_xf)
    aggregate_kernel<<<aggBlocks, 256>>>(d_xf, nNodes, 0);     // 6
    gemm_kernel<<<gemmBlocks, 128>>>(d_mean, d_xf, W1l, b1, W1r,
                                     Wfc, bfc, pred, nNodes, 1);  // 7
    // Layer 2 (+ fused fc head)
    aggregate_kernel<<<aggBlocks, 256>>>(d_h1, nNodes, 0);     // 8
    gemm_kernel<<<gemmBlocks, 128>>>(d_mean, d_h1, W2l, b2, W2r,
                                     Wfc, bfc, pred, nNodes, 2);  // 9
}